// round 1
// baseline (speedup 1.0000x reference)
#include <cuda_runtime.h>
#include <math.h>

// ---------------- model constants ----------------
#define BVAL   32
#define DVAL   768
#define NTOK   197
#define NPATCH 196
#define HEADS  12
#define DKV    64
#define MLPD   3072
#define DEPTH  12
#define MTOK   (BVAL*NTOK)     // 6304
#define MPATCH (BVAL*NPATCH)   // 6272
#define NNSC   (NTOK*NTOK)     // 38809

// ---------------- scratch (static device globals; no allocation) ----------------
__device__ float g_tok[MTOK*DVAL];
__device__ float g_hbuf[MTOK*DVAL];
__device__ float g_q[MTOK*DVAL];
__device__ float g_k[MTOK*DVAL];
__device__ float g_v[MTOK*DVAL];
__device__ float g_ctx[MTOK*DVAL];                 // also reused as patch-conv output
__device__ float g_scores[(long long)BVAL*HEADS*NNSC];
__device__ float g_hid[(long long)MTOK*MLPD];
__device__ float g_col[(long long)MPATCH*DVAL];
__device__ float g_wT[DVAL*DVAL];

__device__ __forceinline__ float gelu_f(float x) {
    return 0.5f * x * (1.0f + erff(x * 0.70710678118654752440f));
}

// ---------------- generic batched SGEMM ----------------
// C[M,N] = op(epilogue)(A[M,K] @ B) ; B is [K,N] row-major (TRANSB=0) or accessed
// as B[n*ldb+k] (TRANSB=1). Batch offset = (z/hdiv)*s?0 + (z%hdiv)*s?1.
// EPI: 0 = store acc ; 1 = store acc+bias ; 2 = store gelu(acc+bias) ; 3 = C += acc+bias
template<int EPI, int TRANSB>
__global__ __launch_bounds__(256)
void sgemm_kernel(int M, int N, int K,
                  const float* __restrict__ A, int lda, long long sA0, long long sA1,
                  const float* __restrict__ Bm, int ldb, long long sB0, long long sB1,
                  float* __restrict__ C, int ldc, long long sC0, long long sC1,
                  const float* __restrict__ bias, int hdiv)
{
    __shared__ float As[16][132];
    __shared__ float Bs[16][132];

    int z  = blockIdx.z;
    int zb = z / hdiv, zh = z - zb * hdiv;
    A  += zb * sA0 + zh * sA1;
    Bm += zb * sB0 + zh * sB1;
    C  += zb * sC0 + zh * sC1;

    int tid = threadIdx.x;
    int tx = tid & 15, ty = tid >> 4;
    int row0 = blockIdx.y * 128, col0 = blockIdx.x * 128;

    float acc[8][8];
    #pragma unroll
    for (int i = 0; i < 8; i++)
        #pragma unroll
        for (int j = 0; j < 8; j++) acc[i][j] = 0.f;

    for (int k0 = 0; k0 < K; k0 += 16) {
        // load A tile (128 rows x 16 k), store transposed As[k][m]
        #pragma unroll
        for (int i = 0; i < 8; i++) {
            int e = tid + i * 256;
            int m = e >> 4, kk = e & 15;
            int gm = row0 + m, gk = k0 + kk;
            float v = 0.f;
            if (gm < M && gk < K) v = A[(long long)gm * lda + gk];
            As[kk][m] = v;
        }
        // load B tile Bs[k][n]
        #pragma unroll
        for (int i = 0; i < 8; i++) {
            int e = tid + i * 256;
            if (TRANSB) {
                int n = e >> 4, kk = e & 15;
                int gn = col0 + n, gk = k0 + kk;
                float v = 0.f;
                if (gn < N && gk < K) v = Bm[(long long)gn * ldb + gk];
                Bs[kk][n] = v;
            } else {
                int n = e & 127, kk = e >> 7;
                int gn = col0 + n, gk = k0 + kk;
                float v = 0.f;
                if (gn < N && gk < K) v = Bm[(long long)gk * ldb + gn];
                Bs[kk][n] = v;
            }
        }
        __syncthreads();

        #pragma unroll
        for (int kk = 0; kk < 16; kk++) {
            float a[8], b[8];
            #pragma unroll
            for (int i = 0; i < 8; i++) a[i] = As[kk][ty * 8 + i];
            #pragma unroll
            for (int j = 0; j < 8; j++) b[j] = Bs[kk][tx * 8 + j];
            #pragma unroll
            for (int i = 0; i < 8; i++)
                #pragma unroll
                for (int j = 0; j < 8; j++)
                    acc[i][j] = fmaf(a[i], b[j], acc[i][j]);
        }
        __syncthreads();
    }

    #pragma unroll
    for (int i = 0; i < 8; i++) {
        int gm = row0 + ty * 8 + i;
        if (gm >= M) continue;
        #pragma unroll
        for (int j = 0; j < 8; j++) {
            int gn = col0 + tx * 8 + j;
            if (gn >= N) continue;
            float r = acc[i][j];
            if (EPI >= 1) r += bias[gn];
            if (EPI == 2) r = gelu_f(r);
            long long idx = (long long)gm * ldc + gn;
            if (EPI == 3) C[idx] += r;
            else          C[idx] = r;
        }
    }
}

// ---------------- LayerNorm (one block per row of 768) ----------------
__global__ void ln_kernel(const float* __restrict__ in, float* __restrict__ out,
                          const float* __restrict__ w, const float* __restrict__ b)
{
    __shared__ float red[256];
    int row = blockIdx.x;
    int tid = threadIdx.x;
    const float* x = in + (long long)row * DVAL;

    float v0 = x[tid], v1 = x[tid + 256], v2 = x[tid + 512];
    red[tid] = v0 + v1 + v2;
    __syncthreads();
    for (int o = 128; o > 0; o >>= 1) { if (tid < o) red[tid] += red[tid + o]; __syncthreads(); }
    float mu = red[0] * (1.0f / 768.0f);
    __syncthreads();

    float d0 = v0 - mu, d1 = v1 - mu, d2 = v2 - mu;
    red[tid] = d0 * d0 + d1 * d1 + d2 * d2;
    __syncthreads();
    for (int o = 128; o > 0; o >>= 1) { if (tid < o) red[tid] += red[tid + o]; __syncthreads(); }
    float rs = rsqrtf(red[0] * (1.0f / 768.0f) + 1e-5f);

    float* y = out + (long long)row * DVAL;
    y[tid]       = d0 * rs * w[tid]       + b[tid];
    y[tid + 256] = d1 * rs * w[tid + 256] + b[tid + 256];
    y[tid + 512] = d2 * rs * w[tid + 512] + b[tid + 512];
}

// ---------------- softmax over last dim (197), warp per row; scale folded in ----------------
__global__ void softmax_kernel(float* __restrict__ s)
{
    int row = blockIdx.x * 8 + (threadIdx.x >> 5);
    if (row >= BVAL * HEADS * NTOK) return;
    int lane = threadIdx.x & 31;
    float* p = s + (long long)row * NTOK;
    const float scale = 0.125f;   // 1/sqrt(64)

    float vals[7];
    float mx = -1e30f;
    #pragma unroll
    for (int i = 0; i < 7; i++) {
        int c = lane + i * 32;
        float v = (c < NTOK) ? p[c] * scale : -1e30f;
        vals[i] = v;
        mx = fmaxf(mx, v);
    }
    #pragma unroll
    for (int o = 16; o > 0; o >>= 1) mx = fmaxf(mx, __shfl_xor_sync(0xffffffffu, mx, o));

    float sum = 0.f;
    #pragma unroll
    for (int i = 0; i < 7; i++) {
        int c = lane + i * 32;
        float e = (c < NTOK) ? expf(vals[i] - mx) : 0.f;
        vals[i] = e;
        sum += e;
    }
    #pragma unroll
    for (int o = 16; o > 0; o >>= 1) sum += __shfl_xor_sync(0xffffffffu, sum, o);
    float inv = 1.0f / sum;

    #pragma unroll
    for (int i = 0; i < 7; i++) {
        int c = lane + i * 32;
        if (c < NTOK) p[c] = vals[i] * inv;
    }
}

// ---------------- patch-embed helpers ----------------
__global__ void transpose_w_kernel(const float* __restrict__ w)  // [768out,768in] -> [768in,768out]
{
    int idx = blockIdx.x * 256 + threadIdx.x;
    if (idx >= DVAL * DVAL) return;
    int k = idx / DVAL, n = idx % DVAL;
    g_wT[k * DVAL + n] = w[n * DVAL + k];
}

__global__ void im2col_kernel(const float* __restrict__ x)  // x [B,3,224,224]
{
    long long idx = (long long)blockIdx.x * blockDim.x + threadIdx.x;
    if (idx >= (long long)MPATCH * DVAL) return;
    int col = (int)(idx % DVAL);
    long long r = idx / DVAL;
    int p = (int)(r % NPATCH);
    int b = (int)(r / NPATCH);
    int c = col >> 8;
    int rem = col & 255;
    int i = rem >> 4, j = rem & 15;
    int py = p / 14, px = p % 14;
    g_col[idx] = x[(((long long)b * 3 + c) * 224 + py * 16 + i) * 224 + px * 16 + j];
}

__global__ void assemble_tok_kernel(const float* __restrict__ patch,
                                    const float* __restrict__ cls,
                                    const float* __restrict__ pos)
{
    long long idx = (long long)blockIdx.x * blockDim.x + threadIdx.x;
    if (idx >= (long long)MTOK * DVAL) return;
    int d = (int)(idx % DVAL);
    long long r = idx / DVAL;
    int n = (int)(r % NTOK);
    int b = (int)(r / NTOK);
    float v;
    if (n == 0) v = cls[d];
    else        v = patch[((long long)b * NPATCH + (n - 1)) * DVAL + d];
    g_tok[idx] = v + pos[n * DVAL + d];
}

// ---------------- head: double-LN on cls + MLP head, one block per batch ----------------
__global__ void head_kernel(const float* __restrict__ tok,
                            const float* __restrict__ fw, const float* __restrict__ fb,
                            const float* __restrict__ hw, const float* __restrict__ hb,
                            const float* __restrict__ h1w, const float* __restrict__ h1b,
                            const float* __restrict__ h2w, const float* __restrict__ h2b,
                            float* __restrict__ out)
{
    __shared__ float cbuf[DVAL];
    __shared__ float hid[MLPD];
    __shared__ float red[256];
    int b = blockIdx.x, tid = threadIdx.x;
    const float* t = tok + (long long)b * NTOK * DVAL;   // cls row

    // ----- LN (fnorm) -----
    float v0 = t[tid], v1 = t[tid + 256], v2 = t[tid + 512];
    red[tid] = v0 + v1 + v2; __syncthreads();
    for (int o = 128; o > 0; o >>= 1) { if (tid < o) red[tid] += red[tid + o]; __syncthreads(); }
    float mu = red[0] * (1.0f / 768.0f); __syncthreads();
    float d0 = v0 - mu, d1 = v1 - mu, d2 = v2 - mu;
    red[tid] = d0 * d0 + d1 * d1 + d2 * d2; __syncthreads();
    for (int o = 128; o > 0; o >>= 1) { if (tid < o) red[tid] += red[tid + o]; __syncthreads(); }
    float rs = rsqrtf(red[0] * (1.0f / 768.0f) + 1e-5f); __syncthreads();
    float u0 = d0 * rs * fw[tid]       + fb[tid];
    float u1 = d1 * rs * fw[tid + 256] + fb[tid + 256];
    float u2 = d2 * rs * fw[tid + 512] + fb[tid + 512];

    // ----- LN (hln) -----
    red[tid] = u0 + u1 + u2; __syncthreads();
    for (int o = 128; o > 0; o >>= 1) { if (tid < o) red[tid] += red[tid + o]; __syncthreads(); }
    mu = red[0] * (1.0f / 768.0f); __syncthreads();
    d0 = u0 - mu; d1 = u1 - mu; d2 = u2 - mu;
    red[tid] = d0 * d0 + d1 * d1 + d2 * d2; __syncthreads();
    for (int o = 128; o > 0; o >>= 1) { if (tid < o) red[tid] += red[tid + o]; __syncthreads(); }
    rs = rsqrtf(red[0] * (1.0f / 768.0f) + 1e-5f); __syncthreads();
    cbuf[tid]       = d0 * rs * hw[tid]       + hb[tid];
    cbuf[tid + 256] = d1 * rs * hw[tid + 256] + hb[tid + 256];
    cbuf[tid + 512] = d2 * rs * hw[tid + 512] + hb[tid + 512];
    __syncthreads();

    // ----- hidden = gelu(c @ h1w + h1b), h1w [768,3072] -----
    for (int j = tid; j < MLPD; j += 256) {
        float sacc = h1b[j];
        for (int d = 0; d < DVAL; d++)
            sacc = fmaf(cbuf[d], h1w[(long long)d * MLPD + j], sacc);
        hid[j] = gelu_f(sacc);
    }
    __syncthreads();

    // ----- logits = hid @ h2w + h2b, h2w [3072,2] -----
    for (int c2 = 0; c2 < 2; c2++) {
        float part = 0.f;
        for (int j = tid; j < MLPD; j += 256)
            part = fmaf(hid[j], h2w[j * 2 + c2], part);
        red[tid] = part; __syncthreads();
        for (int o = 128; o > 0; o >>= 1) { if (tid < o) red[tid] += red[tid + o]; __syncthreads(); }
        if (tid == 0) out[b * 2 + c2] = red[0] + h2b[c2];
        __syncthreads();
    }
}

// ---------------- host-side GEMM dispatch ----------------
static void launch_gemm(int epi, int transb, int M, int N, int K,
                        const float* A, int lda, long long sA0, long long sA1,
                        const float* Bm, int ldb, long long sB0, long long sB1,
                        float* C, int ldc, long long sC0, long long sC1,
                        const float* bias, int batch, int hdiv)
{
    dim3 grid((N + 127) / 128, (M + 127) / 128, batch), blk(256);
#define GEMM_CALL(E, T) sgemm_kernel<E, T><<<grid, blk>>>(M, N, K, A, lda, sA0, sA1, Bm, ldb, sB0, sB1, C, ldc, sC0, sC1, bias, hdiv)
    if (transb == 0) {
        if      (epi == 0) GEMM_CALL(0, 0);
        else if (epi == 1) GEMM_CALL(1, 0);
        else if (epi == 2) GEMM_CALL(2, 0);
        else               GEMM_CALL(3, 0);
    } else {
        if      (epi == 0) GEMM_CALL(0, 1);
        else if (epi == 1) GEMM_CALL(1, 1);
        else if (epi == 2) GEMM_CALL(2, 1);
        else               GEMM_CALL(3, 1);
    }
#undef GEMM_CALL
}

extern "C" void kernel_launch(void* const* d_in, const int* in_sizes, int n_in,
                              void* d_out, int out_size)
{
    const float* x         = (const float*)d_in[0];
    const float* conv_w    = (const float*)d_in[1];
    const float* conv_b    = (const float*)d_in[2];
    const float* cls_token = (const float*)d_in[3];
    const float* pos_embed = (const float*)d_in[4];
    const float* ln1_w     = (const float*)d_in[5];
    const float* ln1_b     = (const float*)d_in[6];
    const float* wq        = (const float*)d_in[7];
    const float* wk        = (const float*)d_in[8];
    const float* wv        = (const float*)d_in[9];
    const float* wo_w      = (const float*)d_in[10];
    const float* wo_b      = (const float*)d_in[11];
    const float* ln2_w     = (const float*)d_in[12];
    const float* ln2_b     = (const float*)d_in[13];
    const float* mlp1_w    = (const float*)d_in[14];
    const float* mlp1_b    = (const float*)d_in[15];
    const float* mlp2_w    = (const float*)d_in[16];
    const float* mlp2_b    = (const float*)d_in[17];
    const float* fnorm_w   = (const float*)d_in[18];
    const float* fnorm_b   = (const float*)d_in[19];
    const float* hln_w     = (const float*)d_in[20];
    const float* hln_b     = (const float*)d_in[21];
    const float* h1_w      = (const float*)d_in[22];
    const float* h1_b      = (const float*)d_in[23];
    const float* h2_w      = (const float*)d_in[24];
    const float* h2_b      = (const float*)d_in[25];

    float *tokp, *hp, *qp, *kp, *vp, *ctxp, *scp, *hidp, *colp, *wtp;
    cudaGetSymbolAddress((void**)&tokp, g_tok);
    cudaGetSymbolAddress((void**)&hp,   g_hbuf);
    cudaGetSymbolAddress((void**)&qp,   g_q);
    cudaGetSymbolAddress((void**)&kp,   g_k);
    cudaGetSymbolAddress((void**)&vp,   g_v);
    cudaGetSymbolAddress((void**)&ctxp, g_ctx);
    cudaGetSymbolAddress((void**)&scp,  g_scores);
    cudaGetSymbolAddress((void**)&hidp, g_hid);
    cudaGetSymbolAddress((void**)&colp, g_col);
    cudaGetSymbolAddress((void**)&wtp,  g_wT);

    // ---- patch embed: im2col + GEMM(gelu+bias) + token assembly ----
    transpose_w_kernel<<<(DVAL * DVAL + 255) / 256, 256>>>(conv_w);
    im2col_kernel<<<(int)(((long long)MPATCH * DVAL + 255) / 256), 256>>>(x);
    launch_gemm(2, 0, MPATCH, DVAL, DVAL,
                colp, DVAL, 0, 0, wtp, DVAL, 0, 0, ctxp, DVAL, 0, 0,
                conv_b, 1, 1);
    assemble_tok_kernel<<<(int)(((long long)MTOK * DVAL + 255) / 256), 256>>>(ctxp, cls_token, pos_embed);

    const long long D2 = (long long)DVAL * DVAL;
    const long long DM = (long long)DVAL * MLPD;

    for (int L = 0; L < DEPTH; L++) {
        // LN1
        ln_kernel<<<MTOK, 256>>>(tokp, hp, ln1_w + L * DVAL, ln1_b + L * DVAL);
        // Q, K, V (no bias)
        launch_gemm(0, 0, MTOK, DVAL, DVAL, hp, DVAL, 0, 0, wq + L * D2, DVAL, 0, 0, qp, DVAL, 0, 0, nullptr, 1, 1);
        launch_gemm(0, 0, MTOK, DVAL, DVAL, hp, DVAL, 0, 0, wk + L * D2, DVAL, 0, 0, kp, DVAL, 0, 0, nullptr, 1, 1);
        launch_gemm(0, 0, MTOK, DVAL, DVAL, hp, DVAL, 0, 0, wv + L * D2, DVAL, 0, 0, vp, DVAL, 0, 0, nullptr, 1, 1);
        // scores = Q @ K^T  (batched over B*H; scale folded into softmax)
        launch_gemm(0, 1, NTOK, NTOK, DKV,
                    qp, DVAL, (long long)NTOK * DVAL, DKV,
                    kp, DVAL, (long long)NTOK * DVAL, DKV,
                    scp, NTOK, (long long)HEADS * NNSC, NNSC,
                    nullptr, BVAL * HEADS, HEADS);
        softmax_kernel<<<(BVAL * HEADS * NTOK) / 8, 256>>>(scp);
        // ctx = attn @ V (batched)
        launch_gemm(0, 0, NTOK, DKV, NTOK,
                    scp, NTOK, (long long)HEADS * NNSC, NNSC,
                    vp, DVAL, (long long)NTOK * DVAL, DKV,
                    ctxp, DVAL, (long long)NTOK * DVAL, DKV,
                    nullptr, BVAL * HEADS, HEADS);
        // tok += ctx @ Wo + bo
        launch_gemm(3, 0, MTOK, DVAL, DVAL, ctxp, DVAL, 0, 0, wo_w + L * D2, DVAL, 0, 0,
                    tokp, DVAL, 0, 0, wo_b + L * DVAL, 1, 1);
        // LN2
        ln_kernel<<<MTOK, 256>>>(tokp, hp, ln2_w + L * DVAL, ln2_b + L * DVAL);
        // hid = gelu(h @ W1 + b1)
        launch_gemm(2, 0, MTOK, MLPD, DVAL, hp, DVAL, 0, 0, mlp1_w + L * DM, MLPD, 0, 0,
                    hidp, MLPD, 0, 0, mlp1_b + L * MLPD, 1, 1);
        // tok += hid @ W2 + b2
        launch_gemm(3, 0, MTOK, DVAL, MLPD, hidp, MLPD, 0, 0, mlp2_w + L * DM, DVAL, 0, 0,
                    tokp, DVAL, 0, 0, mlp2_b + L * DVAL, 1, 1);
    }

    head_kernel<<<BVAL, 256>>>(tokp, fnorm_w, fnorm_b, hln_w, hln_b,
                               h1_w, h1_b, h2_w, h2_b, (float*)d_out);
}